// round 1
// baseline (speedup 1.0000x reference)
#include <cuda_runtime.h>
#include <cuda_bf16.h>
#include <mma.h>
#include <math.h>

using namespace nvcuda;

// Problem constants (B=8192, I=O=512 in the dataset)
#define D        512
#define TM       32          // rows per CTA
#define NW       8           // warps per CTA
#define KWTA     128         // k = 512 * 0.25
#define LDA      528         // bf16 shared A leading dim (pad, 16B-aligned rows)
#define LDC      520         // f32 shared C leading dim
#define MAXB     8192

// Shared memory layout (bytes)
#define OFF_A    0
#define SZ_A     (TM * LDA * 2)            // 33792
#define OFF_P    (OFF_A + SZ_A)            // 33792
#define SZ_P     (TM * LDA * 2)
#define OFF_C    (OFF_P + SZ_P)            // 67584
#define SZ_C     (TM * LDC * 4)            // 66560
#define OFF_S    (OFF_C + SZ_C)            // 134144
#define SZ_S     (TM * LDC * 4)
#define OFF_BM   (OFF_S + SZ_S)            // 200704
#define SZ_BM    (TM * 16 * 4)             // 2048
#define SMEM_BYTES (OFF_BM + SZ_BM)        // 202752

// ---------------- device scratch (no allocations allowed) ----------------
__device__ __nv_bfloat16 g_Wb[D * D];
__device__ __nv_bfloat16 g_Vb[D * D];
__device__ __nv_bfloat16 g_Rb[D * D];
__device__ __nv_bfloat16 g_Rgb[D * D];
__device__ __nv_bfloat16 g_Lb[D * D];
__device__ float g_sg[MAXB * D];
__device__ float g_part[MAXB / TM];
__device__ float g_scalef;

// ---------------- weight conversion ----------------
__global__ void convert_kernel(const float* __restrict__ W, const float* __restrict__ V,
                               const float* __restrict__ R, const float* __restrict__ Rg,
                               const float* __restrict__ L) {
    int n = D * D;
    for (int i = blockIdx.x * blockDim.x + threadIdx.x; i < n; i += gridDim.x * blockDim.x) {
        g_Wb[i]  = __float2bfloat16(W[i]);
        g_Vb[i]  = __float2bfloat16(V[i]);
        g_Rb[i]  = __float2bfloat16(R[i]);
        g_Rgb[i] = __float2bfloat16(Rg[i]);
        g_Lb[i]  = __float2bfloat16(L[i]);
    }
}

// ---------------- exact k-WTA (top-128 of 512, stable tie-break by index) ----
// One warp per row. row: 512 contiguous f32. bm: 16 uint32 mask words.
__device__ __forceinline__ void kwta_warp(const float* __restrict__ row, unsigned* __restrict__ bm) {
    int lane = threadIdx.x & 31;
    unsigned u[16];
#pragma unroll
    for (int j = 0; j < 16; j++) {
        unsigned b = __float_as_uint(row[lane + 32 * j]);
        u[j] = (b & 0x80000000u) ? ~b : (b | 0x80000000u);   // monotone map
    }
    // bitwise radix select of the k-th largest value
    unsigned prefix = 0;
    for (int bit = 31; bit >= 0; --bit) {
        unsigned probe = prefix | (1u << bit);
        int c = 0;
#pragma unroll
        for (int j = 0; j < 16; j++) c += (u[j] >= probe);
        c = __reduce_add_sync(0xffffffffu, c);
        if (c >= KWTA) prefix = probe;
    }
    int cg = 0;
#pragma unroll
    for (int j = 0; j < 16; j++) cg += (u[j] > prefix);
    cg = __reduce_add_sync(0xffffffffu, cg);
    int remk = KWTA - cg;                        // how many ties (==T) to include, lowest index first
    unsigned lmask = (1u << lane) - 1u;
    int running = 0;
#pragma unroll
    for (int j = 0; j < 16; j++) {
        bool eq = (u[j] == prefix);
        unsigned beq = __ballot_sync(0xffffffffu, eq);
        bool inc = (u[j] > prefix) || (eq && (running + __popc(beq & lmask)) < remk);
        running += __popc(beq);
        unsigned w = __ballot_sync(0xffffffffu, inc);
        if (lane == 0) bm[j] = w;                // element index c = lane + 32*j -> word j, bit lane
    }
}

// ---------------- 32xD x DxD GEMM tile (bf16 wmma, fp32 acc) ----------------
// A: shared bf16 [TM][LDA]. B: global bf16 [D][D] (row- or col-major fragment).
// C: shared f32 [TM][LDC].
template <bool BCol>
__device__ __forceinline__ void gemm32(const __nv_bfloat16* __restrict__ As,
                                       const __nv_bfloat16* __restrict__ Bg,
                                       float* __restrict__ Cs) {
    int warp = threadIdx.x >> 5;
    int n0 = warp * 64;
    wmma::fragment<wmma::accumulator, 16, 16, 16, float> acc[2][4];
#pragma unroll
    for (int i = 0; i < 2; i++)
#pragma unroll
        for (int j = 0; j < 4; j++) wmma::fill_fragment(acc[i][j], 0.0f);

    for (int kk = 0; kk < D; kk += 16) {
        wmma::fragment<wmma::matrix_a, 16, 16, 16, __nv_bfloat16, wmma::row_major> a0, a1;
        wmma::load_matrix_sync(a0, As + kk, LDA);
        wmma::load_matrix_sync(a1, As + 16 * LDA + kk, LDA);
#pragma unroll
        for (int j = 0; j < 4; j++) {
            if constexpr (BCol) {
                wmma::fragment<wmma::matrix_b, 16, 16, 16, __nv_bfloat16, wmma::col_major> b;
                wmma::load_matrix_sync(b, Bg + (size_t)(n0 + j * 16) * D + kk, D);
                wmma::mma_sync(acc[0][j], a0, b, acc[0][j]);
                wmma::mma_sync(acc[1][j], a1, b, acc[1][j]);
            } else {
                wmma::fragment<wmma::matrix_b, 16, 16, 16, __nv_bfloat16, wmma::row_major> b;
                wmma::load_matrix_sync(b, Bg + (size_t)kk * D + n0 + j * 16, D);
                wmma::mma_sync(acc[0][j], a0, b, acc[0][j]);
                wmma::mma_sync(acc[1][j], a1, b, acc[1][j]);
            }
        }
    }
#pragma unroll
    for (int i = 0; i < 2; i++)
#pragma unroll
        for (int j = 0; j < 4; j++)
            wmma::store_matrix_sync(Cs + i * 16 * LDC + n0 + j * 16, acc[i][j], LDC, wmma::mem_row_major);
}

// ---------------- fused main kernel ----------------
__global__ void __launch_bounds__(256) fused_kernel(
    const float* __restrict__ bu, const float* __restrict__ td, const float* __restrict__ x,
    const float* __restrict__ xt1, const float* __restrict__ xt2, const float* __restrict__ xt3,
    const float* __restrict__ b_in, const float* __restrict__ b_out) {
    extern __shared__ unsigned char smem[];
    __nv_bfloat16* Abuf = (__nv_bfloat16*)(smem + OFF_A);
    __nv_bfloat16* Pbuf = (__nv_bfloat16*)(smem + OFF_P);
    float* Cbuf = (float*)(smem + OFF_C);
    float* Sg   = (float*)(smem + OFF_S);
    unsigned* BM = (unsigned*)(smem + OFF_BM);
    __shared__ float red[256];

    const int tid = threadIdx.x, warp = tid >> 5;
    const size_t row0 = (size_t)blockIdx.x * TM;
    const float INV_SQRT2 = 0.70710678118654752440f;
    const float INV_SQRT2PI = 0.39894228040143267794f;

    // ---- kwta over x (exact fp32, from global) ----
    for (int r = warp; r < TM; r += NW) kwta_warp(x + (row0 + r) * D, BM + r * 16);
    __syncthreads();

    // ---- phi(x), phi'(x) -> bf16 ----
#pragma unroll 4
    for (int i = 0; i < (TM * D) / 256; i++) {
        int e = tid + 256 * i; int r = e >> 9, c = e & 511;
        float v = x[(row0 + r) * D + c];
        float m = ((BM[r * 16 + (c >> 5)] >> (c & 31)) & 1u) ? 1.0f : 0.0f;
        float cdf = 0.5f * (1.0f + erff(v * INV_SQRT2));
        Abuf[r * LDA + c] = __float2bfloat16(v * cdf * m);
        float pdf = expf(-0.5f * v * v) * INV_SQRT2PI;
        Pbuf[r * LDA + c] = __float2bfloat16((cdf + v * pdf) * m);
    }
    __syncthreads();

    gemm32<false>(Abuf, g_Wb, Cbuf);   // prediction = phi_x @ W
    gemm32<false>(Abuf, g_Lb, Sg);     // Sg = lateral = phi_x @ L
    __syncthreads();

    // ---- error = bu - (pred + b_out) ----
#pragma unroll 4
    for (int i = 0; i < (TM * D) / 256; i++) {
        int e = tid + 256 * i; int r = e >> 9, c = e & 511;
        float er = bu[(row0 + r) * D + c] - (Cbuf[r * LDC + c] + b_out[c]);
        Abuf[r * LDA + c] = __float2bfloat16(er);
    }
    __syncthreads();

    gemm32<true>(Abuf, g_Wb, Cbuf);    // fb = error @ W^T   (col-major frags)
    __syncthreads();

    // ---- Sg += fb * phi'(x); then build x_context into Cbuf ----
#pragma unroll 4
    for (int i = 0; i < (TM * D) / 256; i++) {
        int e = tid + 256 * i; int r = e >> 9, c = e & 511;
        Sg[r * LDC + c] += Cbuf[r * LDC + c] * __bfloat162float(Pbuf[r * LDA + c]);
    }
    __syncthreads();
#pragma unroll 4
    for (int i = 0; i < (TM * D) / 256; i++) {
        int e = tid + 256 * i; int r = e >> 9, c = e & 511;
        size_t gi = (row0 + r) * D + c;
        Cbuf[r * LDC + c] = 0.5f * xt1[gi] + 0.3f * xt2[gi] + 0.2f * xt3[gi];
    }
    __syncthreads();

    // ---- kwta over x_context (from shared, fp32 exact) ----
    for (int r = warp; r < TM; r += NW) kwta_warp(Cbuf + r * LDC, BM + r * 16);
    __syncthreads();

    // ---- x_ctx -> Abuf(bf16), phi(x_ctx) -> Pbuf(bf16) ----
#pragma unroll 4
    for (int i = 0; i < (TM * D) / 256; i++) {
        int e = tid + 256 * i; int r = e >> 9, c = e & 511;
        float v = Cbuf[r * LDC + c];
        float m = ((BM[r * 16 + (c >> 5)] >> (c & 31)) & 1u) ? 1.0f : 0.0f;
        Abuf[r * LDA + c] = __float2bfloat16(v);
        float cdf = 0.5f * (1.0f + erff(v * INV_SQRT2));
        Pbuf[r * LDA + c] = __float2bfloat16(v * cdf * m);
    }
    __syncthreads();

    gemm32<false>(Abuf, g_Rgb, Cbuf);  // gate_pre = x_ctx @ R_gate
    __syncthreads();
#pragma unroll 4
    for (int i = 0; i < (TM * D) / 256; i++) {
        int e = tid + 256 * i; int r = e >> 9, c = e & 511;
        Abuf[r * LDA + c] = __float2bfloat16(1.0f / (1.0f + expf(-Cbuf[r * LDC + c])));
    }
    __syncthreads();

    gemm32<false>(Pbuf, g_Rb, Cbuf);   // recraw = phi_ctx @ R
    __syncthreads();
#pragma unroll 4
    for (int i = 0; i < (TM * D) / 256; i++) {
        int e = tid + 256 * i; int r = e >> 9, c = e & 511;
        Sg[r * LDC + c] += Cbuf[r * LDC + c] * __bfloat162float(Abuf[r * LDA + c]);
    }
    __syncthreads();

    // ---- bottom_up -> bf16, GEMM bu @ V ----
#pragma unroll 4
    for (int i = 0; i < (TM * D) / 256; i++) {
        int e = tid + 256 * i; int r = e >> 9, c = e & 511;
        Abuf[r * LDA + c] = __float2bfloat16(bu[(row0 + r) * D + c]);
    }
    __syncthreads();
    gemm32<false>(Abuf, g_Vb, Cbuf);
    __syncthreads();

    // ---- epilogue: assemble state_grad, write scratch, partial sum of squares ----
    float lsum = 0.0f;
#pragma unroll 4
    for (int i = 0; i < (TM * D) / 256; i++) {
        int e = tid + 256 * i; int r = e >> 9, c = e & 511;
        size_t gi = (row0 + r) * D + c;
        float xv = x[gi];
        float sgn = (xv > 0.0f) ? 1.0f : ((xv < 0.0f) ? -1.0f : 0.0f);
        float g = Sg[r * LDC + c]
                + 1.5f * (Cbuf[r * LDC + c] + b_in[c])
                + 3.0f * td[gi]
                - 5.5f * xv
                - 1e-6f * sgn;
        g_sg[gi] = g;
        lsum += g * g;
    }
    red[tid] = lsum;
    __syncthreads();
    for (int o = 128; o > 0; o >>= 1) {
        if (tid < o) red[tid] += red[tid + o];
        __syncthreads();
    }
    if (tid == 0) g_part[blockIdx.x] = red[0];
}

// ---------------- global norm -> clip scale ----------------
__global__ void reduce_scale_kernel(const int* __restrict__ step_i, int nparts) {
    __shared__ float red[256];
    float s = 0.0f;
    for (int i = threadIdx.x; i < nparts; i += 256) s += g_part[i];
    red[threadIdx.x] = s;
    __syncthreads();
    for (int o = 128; o > 0; o >>= 1) {
        if (threadIdx.x < o) red[threadIdx.x] += red[threadIdx.x + o];
        __syncthreads();
    }
    if (threadIdx.x == 0) {
        float eta = 0.8f / (1.0f + 0.1f * (float)step_i[0]);
        float cc = 0.5f * eta;                   // TAU * eta
        float n = cc * sqrtf(red[0]);
        float sc = (n > 1.0f) ? (1.0f / (n + 1e-8f)) : 1.0f;
        g_scalef = cc * sc;
    }
}

// ---------------- finalize: x_new = clip(x + g * scale, -5, 5) ----------------
__global__ void finalize_kernel(const float* __restrict__ x, float* __restrict__ out, int n4) {
    float f = g_scalef;
    const float4* x4 = (const float4*)x;
    const float4* g4 = (const float4*)g_sg;
    float4* o4 = (float4*)out;
    for (int i = blockIdx.x * blockDim.x + threadIdx.x; i < n4; i += gridDim.x * blockDim.x) {
        float4 xv = x4[i];
        float4 gv = g4[i];
        float4 o;
        o.x = fminf(5.0f, fmaxf(-5.0f, xv.x + gv.x * f));
        o.y = fminf(5.0f, fmaxf(-5.0f, xv.y + gv.y * f));
        o.z = fminf(5.0f, fmaxf(-5.0f, xv.z + gv.z * f));
        o.w = fminf(5.0f, fmaxf(-5.0f, xv.w + gv.w * f));
        o4[i] = o;
    }
}

extern "C" void kernel_launch(void* const* d_in, const int* in_sizes, int n_in,
                              void* d_out, int out_size) {
    const float* bu    = (const float*)d_in[0];
    const float* td    = (const float*)d_in[1];
    const float* x     = (const float*)d_in[2];
    const float* xt1   = (const float*)d_in[3];
    const float* xt2   = (const float*)d_in[4];
    const float* xt3   = (const float*)d_in[5];
    const float* V     = (const float*)d_in[6];
    const float* b_in  = (const float*)d_in[7];
    const float* W     = (const float*)d_in[8];
    const float* b_out = (const float*)d_in[9];
    const float* R     = (const float*)d_in[10];
    const float* Rg    = (const float*)d_in[11];
    const float* L     = (const float*)d_in[12];
    const int*   step  = (const int*)d_in[13];

    int Btot = in_sizes[2] / D;         // 8192
    if (Btot > MAXB) Btot = MAXB;
    int nblocks = Btot / TM;            // 256

    cudaFuncSetAttribute(fused_kernel, cudaFuncAttributeMaxDynamicSharedMemorySize, SMEM_BYTES);

    convert_kernel<<<256, 256>>>(W, V, R, Rg, L);
    fused_kernel<<<nblocks, 256, SMEM_BYTES>>>(bu, td, x, xt1, xt2, xt3, b_in, b_out);
    reduce_scale_kernel<<<1, 256>>>(step, nblocks);
    finalize_kernel<<<1024, 256>>>(x, (float*)d_out, Btot * D / 4);
}

// round 3
// speedup vs baseline: 1.5943x; 1.5943x over previous
#include <cuda_runtime.h>
#include <cuda_bf16.h>
#include <mma.h>
#include <math.h>

using namespace nvcuda;

#define D      512
#define KWTA   128
#define MAXB   8192

// GEMM tiling
#define BM     128
#define BN     128
#define BK     32
#define NK     (D / BK)          // 16
#define LDAS   40                // A smem leading dim (bf16 elems), 80B rows (16B mult)
#define LDBS   136               // B smem leading dim
#define LDE    132               // epilogue f32 staging leading dim
#define STAGE_E (BM * LDAS + BK * LDBS)          // 9472 bf16 elems per stage
#define SMEM_GEMM (3 * STAGE_E * 2)              // 56832 bytes (3 stages)

// ---------------- device scratch ----------------
__device__ __nv_bfloat16 g_Wb[D * D];
__device__ __nv_bfloat16 g_WTb[D * D];
__device__ __nv_bfloat16 g_Vb[D * D];
__device__ __nv_bfloat16 g_Rb[D * D];
__device__ __nv_bfloat16 g_Rgb[D * D];
__device__ __nv_bfloat16 g_Lb[D * D];

__device__ __nv_bfloat16 g_phix[MAXB * D];
__device__ __nv_bfloat16 g_bub[MAXB * D];
__device__ __nv_bfloat16 g_ctx[MAXB * D];
__device__ __nv_bfloat16 g_phic[MAXB * D];
__device__ __nv_bfloat16 g_err[MAXB * D];

__device__ float g_phid[MAXB * D];
__device__ float g_lat[MAXB * D];
__device__ float g_fwd[MAXB * D];
__device__ float g_gate[MAXB * D];
__device__ float g_rec[MAXB * D];
__device__ float g_sg[MAXB * D];

__device__ float g_part[(MAXB / BM) * (D / BN)];
__device__ float g_scalef;

// ---------------- weight conversion (+ W transpose) ----------------
__global__ void convert_kernel(const float* __restrict__ W, const float* __restrict__ V,
                               const float* __restrict__ R, const float* __restrict__ Rg,
                               const float* __restrict__ L) {
    int n = D * D;
    for (int idx = blockIdx.x * blockDim.x + threadIdx.x; idx < n; idx += gridDim.x * blockDim.x) {
        int i = idx >> 9, j = idx & 511;
        float w = W[idx];
        g_Wb[idx]  = __float2bfloat16(w);
        g_WTb[j * D + i] = __float2bfloat16(w);
        g_Vb[idx]  = __float2bfloat16(V[idx]);
        g_Rb[idx]  = __float2bfloat16(R[idx]);
        g_Rgb[idx] = __float2bfloat16(Rg[idx]);
        g_Lb[idx]  = __float2bfloat16(L[idx]);
    }
}

// ---------------- exact register k-WTA (top-128 of 512, stable ties) -------
// Full warp holds one row: v[j] is element lane + 32*j. Produces 0/1 mask m[j].
__device__ __forceinline__ void kwta_reg(const float v[16], float m[16]) {
    int lane = threadIdx.x & 31;
    unsigned u[16];
#pragma unroll
    for (int j = 0; j < 16; j++) {
        unsigned b = __float_as_uint(v[j]);
        u[j] = (b & 0x80000000u) ? ~b : (b | 0x80000000u);   // order-preserving map
    }
    unsigned prefix = 0;
    for (int bit = 31; bit >= 0; --bit) {
        unsigned probe = prefix | (1u << bit);
        int c = 0;
#pragma unroll
        for (int j = 0; j < 16; j++) c += (u[j] >= probe);
        c = __reduce_add_sync(0xffffffffu, c);
        if (c >= KWTA) prefix = probe;
    }
    int cg = 0;
#pragma unroll
    for (int j = 0; j < 16; j++) cg += (u[j] > prefix);
    cg = __reduce_add_sync(0xffffffffu, cg);
    int remk = KWTA - cg;                        // ties included lowest-index first
    unsigned lmask = (1u << lane) - 1u;
    int running = 0;
#pragma unroll
    for (int j = 0; j < 16; j++) {
        bool eq = (u[j] == prefix);
        unsigned beq = __ballot_sync(0xffffffffu, eq);
        bool inc = (u[j] > prefix) || (eq && (running + __popc(beq & lmask)) < remk);
        running += __popc(beq);
        m[j] = inc ? 1.0f : 0.0f;
    }
}

// ---------------- elementwise precompute (one warp per batch row) ----------
__global__ void __launch_bounds__(256) elemwise_kernel(
    const float* __restrict__ x, const float* __restrict__ xt1,
    const float* __restrict__ xt2, const float* __restrict__ xt3,
    const float* __restrict__ bu) {
    const int warp = threadIdx.x >> 5, lane = threadIdx.x & 31;
    const size_t row = (size_t)blockIdx.x * 8 + warp;
    const size_t base = row * D;
    const float INV_SQRT2 = 0.70710678118654752440f;
    const float INV_SQRT2PI = 0.39894228040143267794f;

    float v[16], m[16];
#pragma unroll
    for (int j = 0; j < 16; j++) v[j] = x[base + lane + 32 * j];
    kwta_reg(v, m);
#pragma unroll
    for (int j = 0; j < 16; j++) {
        size_t idx = base + lane + 32 * j;
        float val = v[j];
        float cdf = 0.5f * (1.0f + erff(val * INV_SQRT2));
        float pdf = expf(-0.5f * val * val) * INV_SQRT2PI;
        g_phix[idx] = __float2bfloat16(val * cdf * m[j]);
        g_phid[idx] = (cdf + val * pdf) * m[j];
        g_bub[idx]  = __float2bfloat16(bu[idx]);
    }
    float c[16];
#pragma unroll
    for (int j = 0; j < 16; j++) {
        size_t idx = base + lane + 32 * j;
        c[j] = 0.5f * xt1[idx] + 0.3f * xt2[idx] + 0.2f * xt3[idx];
    }
    kwta_reg(c, m);
#pragma unroll
    for (int j = 0; j < 16; j++) {
        size_t idx = base + lane + 32 * j;
        float val = c[j];
        g_ctx[idx] = __float2bfloat16(val);
        float cdf = 0.5f * (1.0f + erff(val * INV_SQRT2));
        g_phic[idx] = __float2bfloat16(val * cdf * m[j]);
    }
}

// ---------------- cp.async helpers ----------------
__device__ __forceinline__ void cp16(void* s, const void* g) {
    unsigned sa = (unsigned)__cvta_generic_to_shared(s);
    asm volatile("cp.async.cg.shared.global [%0], [%1], 16;" :: "r"(sa), "l"(g));
}

__device__ __forceinline__ void load_stage(__nv_bfloat16* stage,
                                           const __nv_bfloat16* Ag,
                                           const __nv_bfloat16* Bg,
                                           int k0, int tid) {
    __nv_bfloat16* As = stage;
    __nv_bfloat16* Bs = stage + BM * LDAS;
    // A tile: BM(128) x BK(32) bf16 = 512 x 16B chunks
    // B tile: BK(32) x BN(128) bf16 = 512 x 16B chunks
#pragma unroll
    for (int t = 0; t < 2; t++) {
        int task = tid + t * 256;
        int arow = task >> 2, ach = task & 3;
        cp16(As + arow * LDAS + ach * 8, Ag + (size_t)arow * D + k0 + ach * 8);
        int brow = task >> 4, bch = task & 15;
        cp16(Bs + brow * LDBS + bch * 8, Bg + (size_t)(k0 + brow) * D + bch * 8);
    }
}

// ---------------- pipelined GEMM (+ mode-specific fused epilogue) ----------
// mode 0: err  = bu - (phi_x@W + b_out)      -> g_err (bf16)
// mode 1: lat  = phi_x@L                     -> g_lat
// mode 2: fwd  = bu@V + b_in                 -> g_fwd
// mode 3: gate = sigmoid(ctx@R_gate)         -> g_gate
// mode 4: rec  = phi_c@R                     -> g_rec
// mode 5: fb   = err@W^T; full state_grad    -> g_sg + partial sumsq
__global__ void __launch_bounds__(256) gemm_kernel(
    int mode_base,
    const float* __restrict__ bu, const float* __restrict__ b_in,
    const float* __restrict__ b_out, const float* __restrict__ td,
    const float* __restrict__ x) {
    extern __shared__ unsigned char smem_raw[];
    __nv_bfloat16* smem = (__nv_bfloat16*)smem_raw;
    __shared__ float red[256];

    const int tid = threadIdx.x, wid = tid >> 5;
    const int wm = wid >> 2, wn = wid & 3;
    const int mode = (mode_base < 0) ? (int)blockIdx.z : mode_base;
    const int n0 = blockIdx.x * BN, m0 = blockIdx.y * BM;

    const __nv_bfloat16 *A, *B;
    switch (mode) {
        case 0: A = g_phix; B = g_Wb;  break;
        case 1: A = g_phix; B = g_Lb;  break;
        case 2: A = g_bub;  B = g_Vb;  break;
        case 3: A = g_ctx;  B = g_Rgb; break;
        case 4: A = g_phic; B = g_Rb;  break;
        default: A = g_err; B = g_WTb; break;
    }
    const __nv_bfloat16* Ag = A + (size_t)m0 * D;
    const __nv_bfloat16* Bg = B + n0;

    wmma::fragment<wmma::accumulator, 16, 16, 16, float> acc[4][2];
#pragma unroll
    for (int i = 0; i < 4; i++)
#pragma unroll
        for (int j = 0; j < 2; j++) wmma::fill_fragment(acc[i][j], 0.0f);

    // software pipeline: 3 buffers, 2 in flight
    load_stage(smem + 0 * STAGE_E, Ag, Bg, 0, tid);
    asm volatile("cp.async.commit_group;" ::: "memory");
    load_stage(smem + 1 * STAGE_E, Ag, Bg, BK, tid);
    asm volatile("cp.async.commit_group;" ::: "memory");

    for (int ki = 0; ki < NK; ki++) {
        asm volatile("cp.async.wait_group 1;" ::: "memory");
        __syncthreads();
        __nv_bfloat16* As = smem + (ki % 3) * STAGE_E;
        __nv_bfloat16* Bs = As + BM * LDAS;
#pragma unroll
        for (int kk = 0; kk < BK; kk += 16) {
            wmma::fragment<wmma::matrix_a, 16, 16, 16, __nv_bfloat16, wmma::row_major> af[4];
            wmma::fragment<wmma::matrix_b, 16, 16, 16, __nv_bfloat16, wmma::row_major> bf_[2];
#pragma unroll
            for (int i = 0; i < 4; i++)
                wmma::load_matrix_sync(af[i], As + (wm * 64 + i * 16) * LDAS + kk, LDAS);
#pragma unroll
            for (int j = 0; j < 2; j++)
                wmma::load_matrix_sync(bf_[j], Bs + kk * LDBS + wn * 32 + j * 16, LDBS);
#pragma unroll
            for (int i = 0; i < 4; i++)
#pragma unroll
                for (int j = 0; j < 2; j++)
                    wmma::mma_sync(acc[i][j], af[i], bf_[j], acc[i][j]);
        }
        if (ki + 2 < NK) load_stage(smem + ((ki + 2) % 3) * STAGE_E, Ag, Bg, (ki + 2) * BK, tid);
        asm volatile("cp.async.commit_group;" ::: "memory");
    }
    asm volatile("cp.async.wait_group 0;" ::: "memory");

    // epilogue: stage 64 rows at a time through smem (reuses pipeline smem)
    float* Es = (float*)smem_raw;
    float ss = 0.0f;
#pragma unroll 1
    for (int half = 0; half < 2; half++) {
        __syncthreads();
        if (wm == half) {
#pragma unroll
            for (int i = 0; i < 4; i++)
#pragma unroll
                for (int j = 0; j < 2; j++)
                    wmma::store_matrix_sync(Es + (i * 16) * LDE + wn * 32 + j * 16,
                                            acc[i][j], LDE, wmma::mem_row_major);
        }
        __syncthreads();
#pragma unroll 4
        for (int t = 0; t < 32; t++) {
            int idx = t * 256 + tid;
            int r = idx >> 7, c = idx & 127;
            int gr = m0 + half * 64 + r, gc = n0 + c;
            size_t gi = (size_t)gr * D + gc;
            float v = Es[r * LDE + c];
            switch (mode) {
                case 0: { float p = v + b_out[gc]; g_err[gi] = __float2bfloat16(bu[gi] - p); } break;
                case 1: g_lat[gi] = v; break;
                case 2: g_fwd[gi] = v + b_in[gc]; break;
                case 3: g_gate[gi] = 1.0f / (1.0f + expf(-v)); break;
                case 4: g_rec[gi] = v; break;
                default: {
                    float xv = x[gi];
                    float sgn = (xv > 0.0f) ? 1.0f : ((xv < 0.0f) ? -1.0f : 0.0f);
                    float g = v * g_phid[gi] + g_lat[gi] + 1.5f * g_fwd[gi] + 3.0f * td[gi]
                              + g_rec[gi] * g_gate[gi] - 5.5f * xv - 1e-6f * sgn;
                    g_sg[gi] = g;
                    ss += g * g;
                } break;
            }
        }
    }

    if (mode == 5) {
        red[tid] = ss;
        __syncthreads();
        for (int o = 128; o > 0; o >>= 1) {
            if (tid < o) red[tid] += red[tid + o];
            __syncthreads();
        }
        if (tid == 0) g_part[blockIdx.y * gridDim.x + blockIdx.x] = red[0];
    }
}

// ---------------- global norm -> clip scale ----------------
__global__ void reduce_scale_kernel(const int* __restrict__ step_i, int nparts) {
    __shared__ float red[256];
    float s = 0.0f;
    for (int i = threadIdx.x; i < nparts; i += 256) s += g_part[i];
    red[threadIdx.x] = s;
    __syncthreads();
    for (int o = 128; o > 0; o >>= 1) {
        if (threadIdx.x < o) red[threadIdx.x] += red[threadIdx.x + o];
        __syncthreads();
    }
    if (threadIdx.x == 0) {
        float eta = 0.8f / (1.0f + 0.1f * (float)step_i[0]);
        float cc = 0.5f * eta;                   // TAU * eta
        float n = cc * sqrtf(red[0]);
        float sc = (n > 1.0f) ? (1.0f / (n + 1e-8f)) : 1.0f;
        g_scalef = cc * sc;
    }
}

// ---------------- finalize ----------------
__global__ void finalize_kernel(const float* __restrict__ x, float* __restrict__ out, int n4) {
    float f = g_scalef;
    const float4* x4 = (const float4*)x;
    const float4* g4 = (const float4*)g_sg;
    float4* o4 = (float4*)out;
    for (int i = blockIdx.x * blockDim.x + threadIdx.x; i < n4; i += gridDim.x * blockDim.x) {
        float4 xv = x4[i];
        float4 gv = g4[i];
        float4 o;
        o.x = fminf(5.0f, fmaxf(-5.0f, xv.x + gv.x * f));
        o.y = fminf(5.0f, fmaxf(-5.0f, xv.y + gv.y * f));
        o.z = fminf(5.0f, fmaxf(-5.0f, xv.z + gv.z * f));
        o.w = fminf(5.0f, fmaxf(-5.0f, xv.w + gv.w * f));
        o4[i] = o;
    }
}

extern "C" void kernel_launch(void* const* d_in, const int* in_sizes, int n_in,
                              void* d_out, int out_size) {
    const float* bu    = (const float*)d_in[0];
    const float* td    = (const float*)d_in[1];
    const float* x     = (const float*)d_in[2];
    const float* xt1   = (const float*)d_in[3];
    const float* xt2   = (const float*)d_in[4];
    const float* xt3   = (const float*)d_in[5];
    const float* V     = (const float*)d_in[6];
    const float* b_in  = (const float*)d_in[7];
    const float* W     = (const float*)d_in[8];
    const float* b_out = (const float*)d_in[9];
    const float* R     = (const float*)d_in[10];
    const float* Rg    = (const float*)d_in[11];
    const float* L     = (const float*)d_in[12];
    const int*   step  = (const int*)d_in[13];

    int Btot = in_sizes[2] / D;
    if (Btot > MAXB) Btot = MAXB;
    int mtiles = Btot / BM;             // 64

    cudaFuncSetAttribute(gemm_kernel, cudaFuncAttributeMaxDynamicSharedMemorySize, SMEM_GEMM);

    convert_kernel<<<256, 256>>>(W, V, R, Rg, L);
    elemwise_kernel<<<Btot / 8, 256>>>(x, xt1, xt2, xt3, bu);
    gemm_kernel<<<dim3(D / BN, mtiles, 5), 256, SMEM_GEMM>>>(-1, bu, b_in, b_out, td, x);
    gemm_kernel<<<dim3(D / BN, mtiles, 1), 256, SMEM_GEMM>>>(5, bu, b_in, b_out, td, x);
    reduce_scale_kernel<<<1, 256>>>(step, mtiles * (D / BN));
    finalize_kernel<<<1024, 256>>>(x, (float*)d_out, Btot * D / 4);
}